// round 3
// baseline (speedup 1.0000x reference)
#include <cuda_runtime.h>
#include <cstdint>
#include <cstddef>

// Problem dims (fixed by dataset)
#define MM 8192
#define KK 4096
#define NN 4096

// GEMM tiling
#define BM 128
#define BN 256
#define BK 64                       // int8 elems per K-tile
#define KTILES (KK / BK)            // 64
#define GTHREADS 256                // 8 warps: 2 (m) x 4 (n), warp tile 64x64

#define ROWB 80                     // smem row stride (64 data + 16 pad)
#define A_SM (BM * ROWB)
#define B_SM (BN * ROWB)
#define STAGE_BYTES (A_SM + B_SM)
#define SMEM_BYTES (2 * STAGE_BYTES)

// ---------------- scratch (allocation-free) ----------------
__device__ __align__(256) int8_t g_xq[(size_t)MM * KK];   // 32 MB quantized activations
__device__ __align__(256) int8_t g_wq[(size_t)NN * KK];   // 16 MB packed int8 weights
__device__ unsigned int g_absmax_bits;
__device__ int g_w_is_i32;

// ---------------- helpers ----------------
__device__ __forceinline__ uint32_t smem_u32(const void* p) {
    uint32_t a;
    asm("{ .reg .u64 t; cvta.to.shared.u64 t, %1; cvt.u32.u64 %0, t; }" : "=r"(a) : "l"(p));
    return a;
}
__device__ __forceinline__ void cp16(uint32_t dst, const void* src) {
    asm volatile("cp.async.cg.shared.global [%0], [%1], 16;" :: "r"(dst), "l"(src));
}
__device__ __forceinline__ uint32_t lds32(uint32_t a) {
    uint32_t v;
    asm volatile("ld.shared.b32 %0, [%1];" : "=r"(v) : "r"(a));
    return v;
}
// int8 tensor-core mma: D(s32) += A(s8,row) * B(s8,col);  m16n8k32
__device__ __forceinline__ void mma_s8(int* c, const uint32_t* a, const uint32_t* b) {
    asm volatile(
        "mma.sync.aligned.m16n8k32.row.col.s32.s8.s8.s32 "
        "{%0,%1,%2,%3}, {%4,%5,%6,%7}, {%8,%9}, {%0,%1,%2,%3};"
        : "+r"(c[0]), "+r"(c[1]), "+r"(c[2]), "+r"(c[3])
        : "r"(a[0]), "r"(a[1]), "r"(a[2]), "r"(a[3]), "r"(b[0]), "r"(b[1]));
}

// ---------------- pre-passes ----------------
__global__ void k_init() { g_absmax_bits = 0u; }

// Detect whether w_q buffer holds int32-promoted values or packed int8.
// int32 layout: every word is a small value in [-127, 127] (3 sign-ext bytes).
// Packed int8: a random 4-byte word is essentially never in that range.
__global__ void k_detect_w(const int* __restrict__ w) {
    int i32 = 1;
    #pragma unroll
    for (int i = 0; i < 32; ++i) {
        int v = w[i];
        if (v < -127 || v > 127) i32 = 0;
    }
    g_w_is_i32 = i32;
}

__global__ void k_pack_w(const void* __restrict__ w, int n4) {   // n4 = NN*KK/4
    const int mode = g_w_is_i32;
    char4* out = (char4*)g_wq;
    if (mode) {
        const int4* w4 = (const int4*)w;
        for (int i = blockIdx.x * blockDim.x + threadIdx.x; i < n4; i += gridDim.x * blockDim.x) {
            int4 v = w4[i];
            char4 q;
            q.x = (signed char)v.x; q.y = (signed char)v.y;
            q.z = (signed char)v.z; q.w = (signed char)v.w;
            out[i] = q;
        }
    } else {
        const char4* w4 = (const char4*)w;
        for (int i = blockIdx.x * blockDim.x + threadIdx.x; i < n4; i += gridDim.x * blockDim.x)
            out[i] = w4[i];
    }
}

__global__ void k_absmax(const float* __restrict__ x, int n4) {
    const float4* x4 = (const float4*)x;
    float m = 0.f;
    for (int i = blockIdx.x * blockDim.x + threadIdx.x; i < n4; i += gridDim.x * blockDim.x) {
        float4 v = x4[i];
        m = fmaxf(m, fmaxf(fmaxf(fabsf(v.x), fabsf(v.y)), fmaxf(fabsf(v.z), fabsf(v.w))));
    }
    #pragma unroll
    for (int o = 16; o; o >>= 1) m = fmaxf(m, __shfl_xor_sync(0xFFFFFFFFu, m, o));
    __shared__ float sm_[32];
    int lane = threadIdx.x & 31, w = threadIdx.x >> 5;
    if (lane == 0) sm_[w] = m;
    __syncthreads();
    if (w == 0) {
        m = (lane < (int)(blockDim.x >> 5)) ? sm_[lane] : 0.f;
        #pragma unroll
        for (int o = 16; o; o >>= 1) m = fmaxf(m, __shfl_xor_sync(0xFFFFFFFFu, m, o));
        if (lane == 0) atomicMax(&g_absmax_bits, __float_as_uint(m));  // all values >= 0
    }
}

__global__ void k_quant_x(const float* __restrict__ x, int n4) {
    const float inv = 127.0f / __uint_as_float(g_absmax_bits);
    const float4* x4 = (const float4*)x;
    char4* out = (char4*)g_xq;
    for (int i = blockIdx.x * blockDim.x + threadIdx.x; i < n4; i += gridDim.x * blockDim.x) {
        float4 v = x4[i];
        char4 q;
        q.x = (signed char)(int)fminf(fmaxf(rintf(v.x * inv), -127.f), 127.f);
        q.y = (signed char)(int)fminf(fmaxf(rintf(v.y * inv), -127.f), 127.f);
        q.z = (signed char)(int)fminf(fmaxf(rintf(v.z * inv), -127.f), 127.f);
        q.w = (signed char)(int)fminf(fmaxf(rintf(v.w * inv), -127.f), 127.f);
        out[i] = q;
    }
}

// ---------------- int8 tensor-core GEMM ----------------
__global__ __launch_bounds__(GTHREADS, 1)
void k_gemm(float* __restrict__ out,
            const float* __restrict__ s_w,       // [N]
            const float* __restrict__ bias) {    // [N]
    extern __shared__ char smem[];
    const uint32_t sb = smem_u32(smem);
    const int tid = threadIdx.x;
    const int wid = tid >> 5, lane = tid & 31;
    const int m0 = blockIdx.y * BM;
    const int n0 = blockIdx.x * BN;
    const int wm0 = (wid & 1) * 64;              // warp tile origin within CTA tile
    const int wn0 = (wid >> 1) * 64;
    const int qr = lane >> 2;                    // groupID
    const int qc = (lane & 3) * 4;               // k-byte offset

    auto load_tile = [&](int s, int kt) {
        const uint32_t abase = sb + s * STAGE_BYTES;
        const uint32_t bbase = abase + A_SM;
        const int k0 = kt * BK;
        #pragma unroll
        for (int i = tid; i < BM * 4; i += GTHREADS) {
            int r = i >> 2, c = i & 3;
            cp16(abase + r * ROWB + c * 16, g_xq + (size_t)(m0 + r) * KK + k0 + c * 16);
        }
        #pragma unroll
        for (int i = tid; i < BN * 4; i += GTHREADS) {
            int r = i >> 2, c = i & 3;
            cp16(bbase + r * ROWB + c * 16, g_wq + (size_t)(n0 + r) * KK + k0 + c * 16);
        }
    };

    int acc[4][8][4];
    #pragma unroll
    for (int mf = 0; mf < 4; ++mf)
        #pragma unroll
        for (int nf = 0; nf < 8; ++nf)
            #pragma unroll
            for (int r = 0; r < 4; ++r) acc[mf][nf][r] = 0;

    load_tile(0, 0);
    asm volatile("cp.async.commit_group;" ::: "memory");

    for (int kt = 0; kt < KTILES; ++kt) {
        const int s = kt & 1;
        asm volatile("cp.async.wait_group 0;" ::: "memory");
        __syncthreads();
        if (kt + 1 < KTILES) {
            load_tile(s ^ 1, kt + 1);
            asm volatile("cp.async.commit_group;" ::: "memory");
        }
        const uint32_t abase = sb + s * STAGE_BYTES;
        const uint32_t bbase = abase + A_SM;

        #pragma unroll
        for (int ks = 0; ks < 2; ++ks) {
            const int k0s = ks * 32;
            uint32_t a[4][4], b[8][2];
            #pragma unroll
            for (int mf = 0; mf < 4; ++mf) {
                const uint32_t r0 = abase + (uint32_t)(wm0 + mf * 16 + qr) * ROWB + k0s + qc;
                a[mf][0] = lds32(r0);
                a[mf][1] = lds32(r0 + 8 * ROWB);
                a[mf][2] = lds32(r0 + 16);
                a[mf][3] = lds32(r0 + 8 * ROWB + 16);
            }
            #pragma unroll
            for (int nf = 0; nf < 8; ++nf) {
                const uint32_t r0 = bbase + (uint32_t)(wn0 + nf * 8 + qr) * ROWB + k0s + qc;
                b[nf][0] = lds32(r0);
                b[nf][1] = lds32(r0 + 16);
            }
            #pragma unroll
            for (int mf = 0; mf < 4; ++mf)
                #pragma unroll
                for (int nf = 0; nf < 8; ++nf)
                    mma_s8(acc[mf][nf], a[mf], b[nf]);
        }
        __syncthreads();
    }

    // epilogue: y = acc * (s_x * s_w[n]) + bias[n]
    const float s_x = __uint_as_float(g_absmax_bits) * (1.0f / 127.0f);
    const int col_base = n0 + wn0 + (lane & 3) * 2;
    #pragma unroll
    for (int nf = 0; nf < 8; ++nf) {
        const int c0 = col_base + nf * 8;
        const float sc0 = s_x * s_w[c0],     sc1 = s_x * s_w[c0 + 1];
        const float b0  = bias[c0],          b1  = bias[c0 + 1];
        #pragma unroll
        for (int mf = 0; mf < 4; ++mf) {
            const int row = m0 + wm0 + mf * 16 + qr;
            float2 v0, v1;
            v0.x = (float)acc[mf][nf][0] * sc0 + b0;
            v0.y = (float)acc[mf][nf][1] * sc1 + b1;
            v1.x = (float)acc[mf][nf][2] * sc0 + b0;
            v1.y = (float)acc[mf][nf][3] * sc1 + b1;
            *reinterpret_cast<float2*>(out + (size_t)row * NN + c0)       = v0;
            *reinterpret_cast<float2*>(out + (size_t)(row + 8) * NN + c0) = v1;
        }
    }
}

// ---------------- launch ----------------
extern "C" void kernel_launch(void* const* d_in, const int* in_sizes, int n_in,
                              void* d_out, int out_size) {
    const float* x    = (const float*)d_in[0];
    const void*  wq   = d_in[1];                 // int8 or int32-promoted; detected on device
    const float* sw   = (const float*)d_in[2];
    const float* bias = (const float*)d_in[3];
    float* out = (float*)d_out;

    cudaFuncSetAttribute(k_gemm, cudaFuncAttributeMaxDynamicSharedMemorySize, SMEM_BYTES);

    k_init<<<1, 1>>>();
    k_detect_w<<<1, 1>>>((const int*)wq);
    k_pack_w<<<1024, 256>>>(wq, (NN * KK) / 4);
    k_absmax<<<2048, 256>>>(x, (MM * KK) / 4);
    k_quant_x<<<2048, 256>>>(x, (MM * KK) / 4);

    dim3 grid(NN / BN, MM / BM);   // (16, 64)
    k_gemm<<<grid, GTHREADS, SMEM_BYTES>>>(out, sw, bias);
}